// round 2
// baseline (speedup 1.0000x reference)
#include <cuda_runtime.h>
#include <math.h>

#define NN 50000
#define EDG 400000
#define EE 450000      // EDG + NN self loops
#define DIM 64
#define NH 4
#define HD 256         // NH * DIM
#define NL 3
#define NC 10
#define NG 512

// ---------------- scratch (static device globals; no runtime allocation) ----
__device__ float g_x[NN * DIM];        // node features between layers
__device__ float g_xl[NN * HD];        // source transform
__device__ float g_xr[NN * HD];        // target transform
__device__ float g_e[EE * NH];         // per-edge attention logits, then exp()
__device__ float g_emax[NN * NH];      // segment max per (dst, head)
__device__ float g_denom[NN * NH];     // segment sum of exp
__device__ float g_out[NN * HD];       // aggregated messages
__device__ float g_pool[NG * DIM];
__device__ float g_cnt[NG];

// float atomic max via signed-int max / unsigned min trick (monotone encodings)
__device__ __forceinline__ void atomicMaxF(float* addr, float v) {
    if (v >= 0.f) atomicMax((int*)addr, __float_as_int(v));
    else          atomicMin((unsigned int*)addr, __float_as_uint(v));
}

// ---------------- atom encoder: sum of 9 categorical embeddings -------------
__global__ void k_encoder(const int* __restrict__ feat, const float* __restrict__ emb) {
    int t = blockIdx.x * blockDim.x + threadIdx.x;
    if (t >= NN * DIM) return;
    int n = t >> 6, d = t & 63;
    const int offs[9] = {0, 119, 124, 136, 148, 158, 164, 170, 172};
    float s = 0.f;
#pragma unroll
    for (int j = 0; j < 9; j++) {
        int idx = feat[n * 9 + j] + offs[j];
        s += emb[idx * DIM + d];
    }
    g_x[t] = s;
}

// ---------------- fused GEMM: xl = x@Wl + bl, xr = x@Wr + br ----------------
// 64x64 output tile per block, 256 threads, 4x4 register blocking, K=64.
__global__ __launch_bounds__(256) void k_gemm(const float* __restrict__ Wl, const float* __restrict__ bl,
                                              const float* __restrict__ Wr, const float* __restrict__ br) {
    __shared__ float sA[64][65];   // [m][k]
    __shared__ float sB[64][65];   // [k][c]
    int bm = blockIdx.x * 64;
    int bc = blockIdx.y * 64;      // 0..511 virtual column over [Wl | Wr]
    const float* W; const float* bias; float* outp;
    if (bc < HD) { W = Wl; bias = bl; outp = g_xl; }
    else         { W = Wr; bias = br; outp = g_xr; bc -= HD; }

    int tid = threadIdx.x;
    for (int i = tid; i < 64 * 64; i += 256) {
        int m = i >> 6, k = i & 63;
        int row = bm + m;
        sA[m][k] = (row < NN) ? g_x[row * DIM + k] : 0.f;
    }
    for (int i = tid; i < 64 * 64; i += 256) {
        int k = i >> 6, c = i & 63;
        sB[k][c] = W[k * HD + bc + c];
    }
    __syncthreads();

    int tm = (tid >> 4) * 4;
    int tc = (tid & 15) * 4;
    float acc[4][4] = {};
#pragma unroll
    for (int k = 0; k < 64; k++) {
        float a[4], b[4];
#pragma unroll
        for (int i = 0; i < 4; i++) a[i] = sA[tm + i][k];
#pragma unroll
        for (int j = 0; j < 4; j++) b[j] = sB[k][tc + j];
#pragma unroll
        for (int i = 0; i < 4; i++)
#pragma unroll
            for (int j = 0; j < 4; j++)
                acc[i][j] += a[i] * b[j];
    }
#pragma unroll
    for (int i = 0; i < 4; i++) {
        int row = bm + tm + i;
        if (row < NN) {
#pragma unroll
            for (int j = 0; j < 4; j++)
                outp[row * HD + bc + tc + j] = acc[i][j] + bias[bc + tc + j];
        }
    }
}

// ---------------- per-layer scratch init ------------------------------------
__global__ void k_init() {
    int t = blockIdx.x * blockDim.x + threadIdx.x;
    if (t < NN * HD) g_out[t] = 0.f;
    if (t < NN * NH) { g_emax[t] = -INFINITY; g_denom[t] = 0.f; }
}

// ---------------- edge attention logits + segment max -----------------------
// one warp per edge
__global__ void k_score(const int* __restrict__ src, const int* __restrict__ dst,
                        const float* __restrict__ att) {
    int gt = blockIdx.x * blockDim.x + threadIdx.x;
    int e = gt >> 5, lane = gt & 31;
    if (e >= EE) return;
    int s, dn;
    if (e < EDG) { s = src[e]; dn = dst[e]; } else { s = dn = e - EDG; }
    const float* xl = g_xl + s * HD;
    const float* xr = g_xr + dn * HD;
#pragma unroll
    for (int h = 0; h < NH; h++) {
        float v0 = xl[h * 64 + lane]      + xr[h * 64 + lane];
        float v1 = xl[h * 64 + 32 + lane] + xr[h * 64 + 32 + lane];
        v0 = (v0 > 0.f) ? v0 : 0.2f * v0;
        v1 = (v1 > 0.f) ? v1 : 0.2f * v1;
        float p = v0 * att[h * 64 + lane] + v1 * att[h * 64 + 32 + lane];
#pragma unroll
        for (int o = 16; o; o >>= 1) p += __shfl_xor_sync(0xffffffffu, p, o);
        if (lane == 0) {
            g_e[e * NH + h] = p;
            atomicMaxF(&g_emax[dn * NH + h], p);
        }
    }
}

// ---------------- exp(e - max) + segment sum --------------------------------
__global__ void k_exp(const int* __restrict__ dst) {
    int t = blockIdx.x * blockDim.x + threadIdx.x;
    if (t >= EE * NH) return;
    int e = t >> 2, h = t & 3;
    int dn = (e < EDG) ? dst[e] : (e - EDG);
    float ea = expf(g_e[t] - g_emax[dn * NH + h]);
    g_e[t] = ea;
    atomicAdd(&g_denom[dn * NH + h], ea);
}

// ---------------- weighted aggregation: out[dst] += alpha * xl[src] ---------
__global__ void k_agg(const int* __restrict__ src, const int* __restrict__ dst) {
    int gt = blockIdx.x * blockDim.x + threadIdx.x;
    int e = gt >> 5, lane = gt & 31;
    if (e >= EE) return;
    int s, dn;
    if (e < EDG) { s = src[e]; dn = dst[e]; } else { s = dn = e - EDG; }
    const float* xl = g_xl + s * HD;
    float* o = g_out + dn * HD;
#pragma unroll
    for (int h = 0; h < NH; h++) {
        float alpha = g_e[e * NH + h] / g_denom[dn * NH + h];
        atomicAdd(&o[h * 64 + lane],      alpha * xl[h * 64 + lane]);
        atomicAdd(&o[h * 64 + 32 + lane], alpha * xl[h * 64 + 32 + lane]);
    }
}

// ---------------- head mean + bias + (exact) GELU ---------------------------
__global__ void k_mean(const float* __restrict__ gb, int dogelu) {
    int t = blockIdx.x * blockDim.x + threadIdx.x;
    if (t >= NN * DIM) return;
    int n = t >> 6, d = t & 63;
    const float* o = g_out + n * HD;
    float s = 0.25f * (o[d] + o[64 + d] + o[128 + d] + o[192 + d]) + gb[d];
    if (dogelu) s = 0.5f * s * (1.f + erff(s * 0.70710678118654752f));
    g_x[t] = s;
}

// ---------------- global mean pool ------------------------------------------
__global__ void k_poolzero() {
    int t = blockIdx.x * blockDim.x + threadIdx.x;
    if (t < NG * DIM) g_pool[t] = 0.f;
    if (t < NG) g_cnt[t] = 0.f;
}

__global__ void k_pool(const int* __restrict__ batch) {
    int t = blockIdx.x * blockDim.x + threadIdx.x;
    if (t >= NN * DIM) return;
    int n = t >> 6, d = t & 63;
    int gidx = batch[n];
    atomicAdd(&g_pool[gidx * DIM + d], g_x[t]);
    if (d == 0) atomicAdd(&g_cnt[gidx], 1.f);
}

// ---------------- classifier head: out = (pool/cnt) @ Wc + bc ---------------
__global__ void k_final(const float* __restrict__ Wc, const float* __restrict__ bc,
                        float* __restrict__ out) {
    int g = blockIdx.x;
    int lane = threadIdx.x;
    float inv = 1.f / fmaxf(g_cnt[g], 1.f);
    float p0 = g_pool[g * DIM + lane] * inv;
    float p1 = g_pool[g * DIM + 32 + lane] * inv;
#pragma unroll
    for (int c = 0; c < NC; c++) {
        float s = p0 * Wc[lane * NC + c] + p1 * Wc[(lane + 32) * NC + c];
#pragma unroll
        for (int o = 16; o; o >>= 1) s += __shfl_xor_sync(0xffffffffu, s, o);
        if (lane == 0) out[g * NC + c] = s + bc[c];
    }
}

// ---------------- launch -----------------------------------------------------
extern "C" void kernel_launch(void* const* d_in, const int* in_sizes, int n_in,
                              void* d_out, int out_size) {
    (void)in_sizes; (void)n_in; (void)out_size;
    const int*   feat  = (const int*)  d_in[0];
    const int*   econ  = (const int*)  d_in[1];   // [2, E]: src then dst
    const int*   batch = (const int*)  d_in[2];
    const float* emb   = (const float*)d_in[3];
    const float* Wl    = (const float*)d_in[4];   // [L, 64, 256]
    const float* bl    = (const float*)d_in[5];   // [L, 256]
    const float* Wr    = (const float*)d_in[6];
    const float* br    = (const float*)d_in[7];
    const float* att   = (const float*)d_in[8];   // [L, 4, 64]
    const float* gbias = (const float*)d_in[9];   // [L, 64]
    const float* Wc    = (const float*)d_in[10];  // [64, 10]
    const float* bcv   = (const float*)d_in[11];  // [10]
    float* out = (float*)d_out;

    const int* src = econ;
    const int* dst = econ + EDG;

    k_encoder<<<(NN * DIM + 255) / 256, 256>>>(feat, emb);

    for (int l = 0; l < NL; l++) {
        dim3 gg((NN + 63) / 64, 8);
        k_gemm<<<gg, 256>>>(Wl + l * DIM * HD, bl + l * HD,
                            Wr + l * DIM * HD, br + l * HD);
        k_init<<<(NN * HD + 255) / 256, 256>>>();
        k_score<<<(EE * 32 + 255) / 256, 256>>>(src, dst, att + l * NH * DIM);
        k_exp<<<(EE * NH + 255) / 256, 256>>>(dst);
        k_agg<<<(EE * 32 + 255) / 256, 256>>>(src, dst);
        k_mean<<<(NN * DIM + 255) / 256, 256>>>(gbias + l * DIM, (l < NL - 1) ? 1 : 0);
    }

    k_poolzero<<<(NG * DIM + 255) / 256, 256>>>();
    k_pool<<<(NN * DIM + 255) / 256, 256>>>(batch);
    k_final<<<NG, 32>>>(Wc, bcv, out);
}

// round 3
// speedup vs baseline: 2.2704x; 2.2704x over previous
#include <cuda_runtime.h>
#include <math.h>

#define NN 50000
#define EDG 400000
#define DIM 64
#define NH 4
#define HD 256
#define NL 3
#define NC 10
#define NG 512

// ---------------- scratch ----------------------------------------------------
__device__ __align__(16) float g_x[NN * DIM];
__device__ __align__(16) float g_xl[NN * HD];
__device__ __align__(16) float g_xr[NN * HD];
__device__ int   g_deg[NN];
__device__ int   g_rowptr[NN + 1];
__device__ int   g_cursor[NN];
__device__ int   g_csrc[EDG];
__device__ float g_pool[NG * DIM];
__device__ float g_cnt[NG];

// ---------------- atom encoder ----------------------------------------------
__global__ void k_encoder(const int* __restrict__ feat, const float* __restrict__ emb) {
    int t = blockIdx.x * blockDim.x + threadIdx.x;
    if (t >= NN * DIM) return;
    int n = t >> 6, d = t & 63;
    const int offs[9] = {0, 119, 124, 136, 148, 158, 164, 170, 172};
    float s = 0.f;
#pragma unroll
    for (int j = 0; j < 9; j++) {
        int idx = feat[n * 9 + j] + offs[j];
        s += emb[idx * DIM + d];
    }
    g_x[t] = s;
}

// ---------------- CSR build (by dst) -----------------------------------------
__global__ void k_zerodeg() {
    int t = blockIdx.x * blockDim.x + threadIdx.x;
    if (t < NN) g_deg[t] = 0;
}

__global__ void k_hist(const int* __restrict__ dst) {
    int e = blockIdx.x * blockDim.x + threadIdx.x;
    if (e < EDG) atomicAdd(&g_deg[dst[e]], 1);
}

__global__ void k_scan() {
    __shared__ int sh[1024];
    __shared__ int carry;
    int t = threadIdx.x;
    if (t == 0) carry = 0;
    __syncthreads();
    for (int base = 0; base < NN; base += 1024) {
        int i = base + t;
        int v = (i < NN) ? g_deg[i] : 0;
        sh[t] = v;
        __syncthreads();
        for (int o = 1; o < 1024; o <<= 1) {
            int u = (t >= o) ? sh[t - o] : 0;
            __syncthreads();
            sh[t] += u;
            __syncthreads();
        }
        if (i < NN) {
            int ex = carry + sh[t] - v;
            g_rowptr[i] = ex;
            g_cursor[i] = ex;
        }
        __syncthreads();
        if (t == 1023) carry += sh[1023];
        __syncthreads();
    }
    if (t == 0) g_rowptr[NN] = carry;
}

__global__ void k_scatter(const int* __restrict__ src, const int* __restrict__ dst) {
    int e = blockIdx.x * blockDim.x + threadIdx.x;
    if (e < EDG) {
        int d = dst[e];
        int pos = atomicAdd(&g_cursor[d], 1);
        g_csrc[pos] = src[e];
    }
}

// ---------------- fused GEMM: [xl | xr] = x @ [Wl | Wr] + bias ---------------
// tile: M=64, N=128, K=64 (full). 256 threads, 4x8 register blocking.
__global__ __launch_bounds__(256) void k_gemm(const float* __restrict__ Wl, const float* __restrict__ bl,
                                              const float* __restrict__ Wr, const float* __restrict__ br) {
    __shared__ float sA[64][68];    // [k][m], padded
    __shared__ float sB[64][128];   // [k][n]
    int bm = blockIdx.x * 64;
    int bc = blockIdx.y * 128;      // virtual col over [Wl | Wr]
    const float* W; const float* bias; float* outp;
    if (bc < HD) { W = Wl; bias = bl; outp = g_xl; }
    else         { W = Wr; bias = br; outp = g_xr; bc -= HD; }

    int tid = threadIdx.x;
    {   // A load + transpose: g_x rows [bm, bm+64), 64 cols
        int r0 = tid >> 4;            // 0..15
        int c4 = (tid & 15) * 4;
        for (int rr = 0; rr < 64; rr += 16) {
            int row = bm + r0 + rr;
            float4 v = make_float4(0.f, 0.f, 0.f, 0.f);
            if (row < NN) v = *(const float4*)(g_x + (size_t)row * DIM + c4);
            sA[c4 + 0][r0 + rr] = v.x;
            sA[c4 + 1][r0 + rr] = v.y;
            sA[c4 + 2][r0 + rr] = v.z;
            sA[c4 + 3][r0 + rr] = v.w;
        }
    }
    {   // B load: W[k][bc..bc+128)
        int kk0 = tid >> 5;
        int f = (tid & 31) * 4;
        for (int kk = kk0; kk < 64; kk += 8)
            *(float4*)&sB[kk][f] = *(const float4*)(W + (size_t)kk * HD + bc + f);
    }
    __syncthreads();

    int ty = tid >> 4;   // m-group: rows 4*ty..4*ty+3
    int tx = tid & 15;   // n-group: cols 8*tx..8*tx+7
    float acc[4][8] = {};
#pragma unroll 16
    for (int k = 0; k < 64; k++) {
        float4 a  = *(const float4*)&sA[k][ty * 4];
        float4 b0 = *(const float4*)&sB[k][tx * 8];
        float4 b1 = *(const float4*)&sB[k][tx * 8 + 4];
        float av[4] = {a.x, a.y, a.z, a.w};
        float bv[8] = {b0.x, b0.y, b0.z, b0.w, b1.x, b1.y, b1.z, b1.w};
#pragma unroll
        for (int i = 0; i < 4; i++)
#pragma unroll
            for (int j = 0; j < 8; j++)
                acc[i][j] += av[i] * bv[j];
    }

    float bia[8];
#pragma unroll
    for (int j = 0; j < 8; j++) bia[j] = bias[bc + tx * 8 + j];
#pragma unroll
    for (int i = 0; i < 4; i++) {
        int row = bm + ty * 4 + i;
        if (row < NN) {
            float4 o0 = make_float4(acc[i][0] + bia[0], acc[i][1] + bia[1],
                                    acc[i][2] + bia[2], acc[i][3] + bia[3]);
            float4 o1 = make_float4(acc[i][4] + bia[4], acc[i][5] + bia[5],
                                    acc[i][6] + bia[6], acc[i][7] + bia[7]);
            *(float4*)(outp + (size_t)row * HD + bc + tx * 8)     = o0;
            *(float4*)(outp + (size_t)row * HD + bc + tx * 8 + 4) = o1;
        }
    }
}

// ---------------- fused attention: score + softmax + aggregate + mean --------
// one warp per destination node; lane owns floats [8*lane, 8*lane+8) = head lane>>3
__device__ __forceinline__ float lrelu(float v) { return v > 0.f ? v : 0.2f * v; }

__device__ __forceinline__ float edge_score(float4 ta, float4 tb,
                                            float4 xra, float4 xrb,
                                            float4 ata, float4 atb) {
    float p = lrelu(ta.x + xra.x) * ata.x + lrelu(ta.y + xra.y) * ata.y
            + lrelu(ta.z + xra.z) * ata.z + lrelu(ta.w + xra.w) * ata.w
            + lrelu(tb.x + xrb.x) * atb.x + lrelu(tb.y + xrb.y) * atb.y
            + lrelu(tb.z + xrb.z) * atb.z + lrelu(tb.w + xrb.w) * atb.w;
    p += __shfl_xor_sync(0xffffffffu, p, 1);
    p += __shfl_xor_sync(0xffffffffu, p, 2);
    p += __shfl_xor_sync(0xffffffffu, p, 4);
    return p;   // per-head score, replicated across the 8-lane oct
}

__global__ __launch_bounds__(256) void k_attn(const float* __restrict__ att,
                                              const float* __restrict__ gb, int dogelu) {
    int w = (blockIdx.x * blockDim.x + threadIdx.x) >> 5;
    int lane = threadIdx.x & 31;
    if (w >= NN) return;

    const float4* xr4 = (const float4*)(g_xr + (size_t)w * HD);
    float4 xra = xr4[2 * lane], xrb = xr4[2 * lane + 1];
    const float4* at4 = (const float4*)att;
    float4 ata = at4[2 * lane], atb = at4[2 * lane + 1];

    // self-loop source row
    const float4* xs4 = (const float4*)(g_xl + (size_t)w * HD);
    float4 sa = xs4[2 * lane], sb = xs4[2 * lane + 1];

    int beg = g_rowptr[w], end = g_rowptr[w + 1];
    int j = beg;
    bool have = (j < end);
    float4 na, nb;
    if (have) {
        int s = g_csrc[j];
        const float4* p = (const float4*)(g_xl + (size_t)s * HD);
        na = p[2 * lane]; nb = p[2 * lane + 1];
    }

    float denom;
    float acc[8];
    {
        float e = edge_score(sa, sb, xra, xrb, ata, atb);
        float ea = __expf(e);
        denom = ea;
        acc[0] = ea * sa.x; acc[1] = ea * sa.y; acc[2] = ea * sa.z; acc[3] = ea * sa.w;
        acc[4] = ea * sb.x; acc[5] = ea * sb.y; acc[6] = ea * sb.z; acc[7] = ea * sb.w;
    }
    while (have) {
        float4 ta = na, tb = nb;
        j++;
        have = (j < end);
        if (have) {
            int s = g_csrc[j];
            const float4* p = (const float4*)(g_xl + (size_t)s * HD);
            na = p[2 * lane]; nb = p[2 * lane + 1];
        }
        float e = edge_score(ta, tb, xra, xrb, ata, atb);
        float ea = __expf(e);
        denom += ea;
        acc[0] += ea * ta.x; acc[1] += ea * ta.y; acc[2] += ea * ta.z; acc[3] += ea * ta.w;
        acc[4] += ea * tb.x; acc[5] += ea * tb.y; acc[6] += ea * tb.z; acc[7] += ea * tb.w;
    }

    float inv = 1.f / denom;   // per-head denom (replicated across oct)
    float r[8];
#pragma unroll
    for (int c = 0; c < 8; c++) {
        float v = acc[c] * inv;
        v += __shfl_xor_sync(0xffffffffu, v, 8);    // sum the 4 heads
        v += __shfl_xor_sync(0xffffffffu, v, 16);
        v *= 0.25f;
        r[c] = v;
    }
    int d0 = 8 * (lane & 7);
#pragma unroll
    for (int c = 0; c < 8; c++) {
        float s = r[c] + gb[d0 + c];
        if (dogelu) s = 0.5f * s * (1.f + erff(s * 0.70710678118654752f));
        r[c] = s;
    }
    if (lane < 8) {
        *(float4*)(g_x + (size_t)w * DIM + d0)     = make_float4(r[0], r[1], r[2], r[3]);
        *(float4*)(g_x + (size_t)w * DIM + d0 + 4) = make_float4(r[4], r[5], r[6], r[7]);
    }
}

// ---------------- global mean pool + head ------------------------------------
__global__ void k_poolzero() {
    int t = blockIdx.x * blockDim.x + threadIdx.x;
    if (t < NG * DIM) g_pool[t] = 0.f;
    if (t < NG) g_cnt[t] = 0.f;
}

__global__ void k_pool(const int* __restrict__ batch) {
    int t = blockIdx.x * blockDim.x + threadIdx.x;
    if (t >= NN * DIM) return;
    int n = t >> 6, d = t & 63;
    int gidx = batch[n];
    atomicAdd(&g_pool[gidx * DIM + d], g_x[t]);
    if (d == 0) atomicAdd(&g_cnt[gidx], 1.f);
}

__global__ void k_final(const float* __restrict__ Wc, const float* __restrict__ bc,
                        float* __restrict__ out) {
    int g = blockIdx.x;
    int lane = threadIdx.x;
    float inv = 1.f / fmaxf(g_cnt[g], 1.f);
    float p0 = g_pool[g * DIM + lane] * inv;
    float p1 = g_pool[g * DIM + 32 + lane] * inv;
#pragma unroll
    for (int c = 0; c < NC; c++) {
        float s = p0 * Wc[lane * NC + c] + p1 * Wc[(lane + 32) * NC + c];
#pragma unroll
        for (int o = 16; o; o >>= 1) s += __shfl_xor_sync(0xffffffffu, s, o);
        if (lane == 0) out[g * NC + c] = s + bc[c];
    }
}

// ---------------- launch ------------------------------------------------------
extern "C" void kernel_launch(void* const* d_in, const int* in_sizes, int n_in,
                              void* d_out, int out_size) {
    (void)in_sizes; (void)n_in; (void)out_size;
    const int*   feat  = (const int*)  d_in[0];
    const int*   econ  = (const int*)  d_in[1];
    const int*   batch = (const int*)  d_in[2];
    const float* emb   = (const float*)d_in[3];
    const float* Wl    = (const float*)d_in[4];
    const float* bl    = (const float*)d_in[5];
    const float* Wr    = (const float*)d_in[6];
    const float* br    = (const float*)d_in[7];
    const float* att   = (const float*)d_in[8];
    const float* gbias = (const float*)d_in[9];
    const float* Wc    = (const float*)d_in[10];
    const float* bcv   = (const float*)d_in[11];
    float* out = (float*)d_out;

    const int* src = econ;
    const int* dst = econ + EDG;

    k_encoder<<<(NN * DIM + 255) / 256, 256>>>(feat, emb);

    // CSR by dst (once per launch)
    k_zerodeg<<<(NN + 255) / 256, 256>>>();
    k_hist<<<(EDG + 255) / 256, 256>>>(dst);
    k_scan<<<1, 1024>>>();
    k_scatter<<<(EDG + 255) / 256, 256>>>(src, dst);

    for (int l = 0; l < NL; l++) {
        dim3 gg((NN + 63) / 64, 4);
        k_gemm<<<gg, 256>>>(Wl + l * DIM * HD, bl + l * HD,
                            Wr + l * DIM * HD, br + l * HD);
        k_attn<<<(NN * 32 + 255) / 256, 256>>>(att + l * NH * DIM, gbias + l * DIM,
                                               (l < NL - 1) ? 1 : 0);
    }

    k_poolzero<<<(NG * DIM + 255) / 256, 256>>>();
    k_pool<<<(NN * DIM + 255) / 256, 256>>>(batch);
    k_final<<<NG, 32>>>(Wc, bcv, out);
}

// round 4
// speedup vs baseline: 2.4811x; 1.0928x over previous
#include <cuda_runtime.h>
#include <math.h>

#define NN 50000
#define EDG 400000
#define DIM 64
#define NH 4
#define HD 256
#define NL 3
#define NC 10
#define NG 512
#define SCAN_B 1024
#define NSB ((NN + SCAN_B - 1) / SCAN_B)   // 49

typedef unsigned long long u64;

// ---------------- scratch ----------------------------------------------------
__device__ __align__(16) float g_x[NN * DIM];
__device__ __align__(16) float g_xl[NN * HD];
__device__ __align__(16) float g_xr[NN * HD];
__device__ int   g_deg[NN];
__device__ int   g_rowptr[NN + 1];
__device__ int   g_cursor[NN];
__device__ int   g_csrc[EDG];
__device__ int   g_bsum[64];
__device__ int   g_boff[64];
__device__ float g_pool[NG * DIM];
__device__ float g_cnt[NG];

// ---------------- f32x2 packed helpers ---------------------------------------
__device__ __forceinline__ u64 pack2(float lo, float hi) {
    u64 r; asm("mov.b64 %0, {%1,%2};" : "=l"(r) : "f"(lo), "f"(hi)); return r;
}
__device__ __forceinline__ void fma2(u64& d, u64 a, u64 b) {
    asm("fma.rn.f32x2 %0, %1, %2, %0;" : "+l"(d) : "l"(a), "l"(b));
}
__device__ __forceinline__ float2 unpack2(u64 v) {
    float2 f; asm("mov.b64 {%0,%1}, %2;" : "=f"(f.x), "=f"(f.y) : "l"(v)); return f;
}

// ---------------- atom encoder ----------------------------------------------
__global__ void k_encoder(const int* __restrict__ feat, const float* __restrict__ emb) {
    int t = blockIdx.x * blockDim.x + threadIdx.x;
    if (t >= NN * DIM) return;
    int n = t >> 6, d = t & 63;
    const int offs[9] = {0, 119, 124, 136, 148, 158, 164, 170, 172};
    float s = 0.f;
#pragma unroll
    for (int j = 0; j < 9; j++) {
        int idx = feat[n * 9 + j] + offs[j];
        s += emb[idx * DIM + d];
    }
    g_x[t] = s;
}

// ---------------- CSR build (by dst) -----------------------------------------
__global__ void k_zerodeg() {
    int t = blockIdx.x * blockDim.x + threadIdx.x;
    if (t < NN) g_deg[t] = 0;
}

__global__ void k_hist(const int* __restrict__ dst) {
    int e = blockIdx.x * blockDim.x + threadIdx.x;
    if (e < EDG) atomicAdd(&g_deg[dst[e]], 1);
}

// phase A: per-block exclusive scan; block sum out
__global__ __launch_bounds__(SCAN_B) void k_scanA() {
    __shared__ int sh[SCAN_B];
    int b = blockIdx.x, t = threadIdx.x;
    int i = b * SCAN_B + t;
    int v = (i < NN) ? g_deg[i] : 0;
    sh[t] = v;
    __syncthreads();
    for (int o = 1; o < SCAN_B; o <<= 1) {
        int u = (t >= o) ? sh[t - o] : 0;
        __syncthreads();
        sh[t] += u;
        __syncthreads();
    }
    if (i < NN) g_rowptr[i] = sh[t] - v;          // block-local exclusive
    if (t == SCAN_B - 1) g_bsum[b] = sh[t];
}

// phase B: scan the 49 block sums (1 block)
__global__ void k_scanB() {
    __shared__ int sh[64];
    int t = threadIdx.x;
    int v = (t < NSB) ? g_bsum[t] : 0;
    sh[t] = v;
    __syncthreads();
    for (int o = 1; o < 64; o <<= 1) {
        int u = (t >= o) ? sh[t - o] : 0;
        __syncthreads();
        sh[t] += u;
        __syncthreads();
    }
    g_boff[t] = sh[t] - v;                        // exclusive block offset
    if (t == NSB - 1) g_rowptr[NN] = sh[t];       // grand total
}

// phase C: add block offsets, init cursors
__global__ void k_scanC() {
    int i = blockIdx.x * blockDim.x + threadIdx.x;
    if (i < NN) {
        int r = g_rowptr[i] + g_boff[i / SCAN_B];
        g_rowptr[i] = r;
        g_cursor[i] = r;
    }
}

__global__ void k_scatter(const int* __restrict__ src, const int* __restrict__ dst) {
    int e = blockIdx.x * blockDim.x + threadIdx.x;
    if (e < EDG) {
        int d = dst[e];
        int pos = atomicAdd(&g_cursor[d], 1);
        g_csrc[pos] = src[e];
    }
}

// ---------------- fused GEMM: [xl | xr] = x @ [Wl | Wr] + bias ---------------
// tile M=64, N=128, K=64. 256 threads, 4x8 blocking via packed f32x2 FMA.
__global__ __launch_bounds__(256) void k_gemm(const float* __restrict__ Wl, const float* __restrict__ bl,
                                              const float* __restrict__ Wr, const float* __restrict__ br) {
    __shared__ float sA[64][68];    // [k][m], padded (272B row = 17*16 ok for float4)
    __shared__ float sB[64][128];   // [k][n]
    int bm = blockIdx.x * 64;
    int bc = blockIdx.y * 128;
    const float* W; const float* bias; float* outp;
    if (bc < HD) { W = Wl; bias = bl; outp = g_xl; }
    else         { W = Wr; bias = br; outp = g_xr; bc -= HD; }

    int tid = threadIdx.x;
    {   // A load + transpose
        int r0 = tid >> 4;
        int c4 = (tid & 15) * 4;
        for (int rr = 0; rr < 64; rr += 16) {
            int row = bm + r0 + rr;
            float4 v = make_float4(0.f, 0.f, 0.f, 0.f);
            if (row < NN) v = *(const float4*)(g_x + (size_t)row * DIM + c4);
            sA[c4 + 0][r0 + rr] = v.x;
            sA[c4 + 1][r0 + rr] = v.y;
            sA[c4 + 2][r0 + rr] = v.z;
            sA[c4 + 3][r0 + rr] = v.w;
        }
    }
    {   // B load
        int kk0 = tid >> 5;
        int f = (tid & 31) * 4;
        for (int kk = kk0; kk < 64; kk += 8)
            *(float4*)&sB[kk][f] = *(const float4*)(W + (size_t)kk * HD + bc + f);
    }
    __syncthreads();

    int ty = tid >> 4;   // rows 4*ty..4*ty+3
    int tx = tid & 15;   // cols 8*tx..8*tx+7
    u64 acc[4][4] = {};  // [row][col-pair]
#pragma unroll 16
    for (int k = 0; k < 64; k++) {
        float4 a = *(const float4*)&sA[k][ty * 4];
        ulonglong2 B0 = *(const ulonglong2*)&sB[k][tx * 8];      // pairs (0,1),(2,3)
        ulonglong2 B1 = *(const ulonglong2*)&sB[k][tx * 8 + 4];  // pairs (4,5),(6,7)
        u64 a0 = pack2(a.x, a.x), a1 = pack2(a.y, a.y);
        u64 a2 = pack2(a.z, a.z), a3 = pack2(a.w, a.w);
        fma2(acc[0][0], a0, B0.x); fma2(acc[0][1], a0, B0.y);
        fma2(acc[0][2], a0, B1.x); fma2(acc[0][3], a0, B1.y);
        fma2(acc[1][0], a1, B0.x); fma2(acc[1][1], a1, B0.y);
        fma2(acc[1][2], a1, B1.x); fma2(acc[1][3], a1, B1.y);
        fma2(acc[2][0], a2, B0.x); fma2(acc[2][1], a2, B0.y);
        fma2(acc[2][2], a2, B1.x); fma2(acc[2][3], a2, B1.y);
        fma2(acc[3][0], a3, B0.x); fma2(acc[3][1], a3, B0.y);
        fma2(acc[3][2], a3, B1.x); fma2(acc[3][3], a3, B1.y);
    }

    float bia[8];
#pragma unroll
    for (int j = 0; j < 8; j++) bia[j] = bias[bc + tx * 8 + j];
#pragma unroll
    for (int i = 0; i < 4; i++) {
        int row = bm + ty * 4 + i;
        if (row < NN) {
            float2 p0 = unpack2(acc[i][0]), p1 = unpack2(acc[i][1]);
            float2 p2 = unpack2(acc[i][2]), p3 = unpack2(acc[i][3]);
            float4 o0 = make_float4(p0.x + bia[0], p0.y + bia[1], p1.x + bia[2], p1.y + bia[3]);
            float4 o1 = make_float4(p2.x + bia[4], p2.y + bia[5], p3.x + bia[6], p3.y + bia[7]);
            *(float4*)(outp + (size_t)row * HD + bc + tx * 8)     = o0;
            *(float4*)(outp + (size_t)row * HD + bc + tx * 8 + 4) = o1;
        }
    }
}

// ---------------- fused attention: score + softmax + aggregate + mean --------
__device__ __forceinline__ float lrelu(float v) { return v > 0.f ? v : 0.2f * v; }

__device__ __forceinline__ float edge_score(float4 ta, float4 tb,
                                            float4 xra, float4 xrb,
                                            float4 ata, float4 atb) {
    float p = lrelu(ta.x + xra.x) * ata.x + lrelu(ta.y + xra.y) * ata.y
            + lrelu(ta.z + xra.z) * ata.z + lrelu(ta.w + xra.w) * ata.w
            + lrelu(tb.x + xrb.x) * atb.x + lrelu(tb.y + xrb.y) * atb.y
            + lrelu(tb.z + xrb.z) * atb.z + lrelu(tb.w + xrb.w) * atb.w;
    p += __shfl_xor_sync(0xffffffffu, p, 1);
    p += __shfl_xor_sync(0xffffffffu, p, 2);
    p += __shfl_xor_sync(0xffffffffu, p, 4);
    return p;   // per-head score, replicated across the 8-lane oct
}

__global__ __launch_bounds__(256) void k_attn(const float* __restrict__ att,
                                              const float* __restrict__ gb, int dogelu) {
    int w = (blockIdx.x * blockDim.x + threadIdx.x) >> 5;
    int lane = threadIdx.x & 31;
    if (w >= NN) return;

    const float4* xr4 = (const float4*)(g_xr + (size_t)w * HD);
    float4 xra = xr4[2 * lane], xrb = xr4[2 * lane + 1];
    const float4* at4 = (const float4*)att;
    float4 ata = at4[2 * lane], atb = at4[2 * lane + 1];

    const float4* xs4 = (const float4*)(g_xl + (size_t)w * HD);
    float4 sa = xs4[2 * lane], sb = xs4[2 * lane + 1];

    int beg = g_rowptr[w], end = g_rowptr[w + 1];
    int j = beg;
    bool have = (j < end);
    float4 na, nb;
    if (have) {
        int s = g_csrc[j];
        const float4* p = (const float4*)(g_xl + (size_t)s * HD);
        na = p[2 * lane]; nb = p[2 * lane + 1];
    }

    float denom;
    float acc[8];
    {
        float e = edge_score(sa, sb, xra, xrb, ata, atb);
        float ea = __expf(e);
        denom = ea;
        acc[0] = ea * sa.x; acc[1] = ea * sa.y; acc[2] = ea * sa.z; acc[3] = ea * sa.w;
        acc[4] = ea * sb.x; acc[5] = ea * sb.y; acc[6] = ea * sb.z; acc[7] = ea * sb.w;
    }
    while (have) {
        float4 ta = na, tb = nb;
        j++;
        have = (j < end);
        if (have) {
            int s = g_csrc[j];
            const float4* p = (const float4*)(g_xl + (size_t)s * HD);
            na = p[2 * lane]; nb = p[2 * lane + 1];
        }
        float e = edge_score(ta, tb, xra, xrb, ata, atb);
        float ea = __expf(e);
        denom += ea;
        acc[0] += ea * ta.x; acc[1] += ea * ta.y; acc[2] += ea * ta.z; acc[3] += ea * ta.w;
        acc[4] += ea * tb.x; acc[5] += ea * tb.y; acc[6] += ea * tb.z; acc[7] += ea * tb.w;
    }

    float inv = 1.f / denom;
    float r[8];
#pragma unroll
    for (int c = 0; c < 8; c++) {
        float v = acc[c] * inv;
        v += __shfl_xor_sync(0xffffffffu, v, 8);
        v += __shfl_xor_sync(0xffffffffu, v, 16);
        v *= 0.25f;
        r[c] = v;
    }
    int d0 = 8 * (lane & 7);
#pragma unroll
    for (int c = 0; c < 8; c++) {
        float s = r[c] + gb[d0 + c];
        if (dogelu) s = 0.5f * s * (1.f + erff(s * 0.70710678118654752f));
        r[c] = s;
    }
    if (lane < 8) {
        *(float4*)(g_x + (size_t)w * DIM + d0)     = make_float4(r[0], r[1], r[2], r[3]);
        *(float4*)(g_x + (size_t)w * DIM + d0 + 4) = make_float4(r[4], r[5], r[6], r[7]);
    }
}

// ---------------- global mean pool + head ------------------------------------
__global__ void k_poolzero() {
    int t = blockIdx.x * blockDim.x + threadIdx.x;
    if (t < NG * DIM) g_pool[t] = 0.f;
    if (t < NG) g_cnt[t] = 0.f;
}

__global__ void k_pool(const int* __restrict__ batch) {
    int t = blockIdx.x * blockDim.x + threadIdx.x;
    if (t >= NN * DIM) return;
    int n = t >> 6, d = t & 63;
    int gidx = batch[n];
    atomicAdd(&g_pool[gidx * DIM + d], g_x[t]);
    if (d == 0) atomicAdd(&g_cnt[gidx], 1.f);
}

__global__ void k_final(const float* __restrict__ Wc, const float* __restrict__ bc,
                        float* __restrict__ out) {
    int g = blockIdx.x;
    int lane = threadIdx.x;
    float inv = 1.f / fmaxf(g_cnt[g], 1.f);
    float p0 = g_pool[g * DIM + lane] * inv;
    float p1 = g_pool[g * DIM + 32 + lane] * inv;
#pragma unroll
    for (int c = 0; c < NC; c++) {
        float s = p0 * Wc[lane * NC + c] + p1 * Wc[(lane + 32) * NC + c];
#pragma unroll
        for (int o = 16; o; o >>= 1) s += __shfl_xor_sync(0xffffffffu, s, o);
        if (lane == 0) out[g * NC + c] = s + bc[c];
    }
}

// ---------------- launch ------------------------------------------------------
extern "C" void kernel_launch(void* const* d_in, const int* in_sizes, int n_in,
                              void* d_out, int out_size) {
    (void)in_sizes; (void)n_in; (void)out_size;
    const int*   feat  = (const int*)  d_in[0];
    const int*   econ  = (const int*)  d_in[1];
    const int*   batch = (const int*)  d_in[2];
    const float* emb   = (const float*)d_in[3];
    const float* Wl    = (const float*)d_in[4];
    const float* bl    = (const float*)d_in[5];
    const float* Wr    = (const float*)d_in[6];
    const float* br    = (const float*)d_in[7];
    const float* att   = (const float*)d_in[8];
    const float* gbias = (const float*)d_in[9];
    const float* Wc    = (const float*)d_in[10];
    const float* bcv   = (const float*)d_in[11];
    float* out = (float*)d_out;

    const int* src = econ;
    const int* dst = econ + EDG;

    k_encoder<<<(NN * DIM + 255) / 256, 256>>>(feat, emb);

    k_zerodeg<<<(NN + 255) / 256, 256>>>();
    k_hist<<<(EDG + 255) / 256, 256>>>(dst);
    k_scanA<<<NSB, SCAN_B>>>();
    k_scanB<<<1, 64>>>();
    k_scanC<<<(NN + 255) / 256, 256>>>();
    k_scatter<<<(EDG + 255) / 256, 256>>>(src, dst);

    for (int l = 0; l < NL; l++) {
        dim3 gg((NN + 63) / 64, 4);
        k_gemm<<<gg, 256>>>(Wl + l * DIM * HD, bl + l * HD,
                            Wr + l * DIM * HD, br + l * HD);
        k_attn<<<(NN * 32 + 255) / 256, 256>>>(att + l * NH * DIM, gbias + l * DIM,
                                               (l < NL - 1) ? 1 : 0);
    }

    k_poolzero<<<(NG * DIM + 255) / 256, 256>>>();
    k_pool<<<(NN * DIM + 255) / 256, 256>>>(batch);
    k_final<<<NG, 32>>>(Wc, bcv, out);
}

// round 8
// speedup vs baseline: 3.5385x; 1.4262x over previous
#include <cuda_runtime.h>
#include <cuda_bf16.h>
#include <math.h>
#include <cstdint>

#define NN 50000
#define EDG 400000
#define DIM 64
#define NH 4
#define HD 256
#define NL 3
#define NC 10
#define NG 512
#define SCAN_B 1024
#define NSB ((NN + SCAN_B - 1) / SCAN_B)

typedef unsigned long long u64;
typedef unsigned int u32;

// ---------------- scratch ----------------------------------------------------
__device__ __align__(16) float g_x[NN * DIM];
__device__ __align__(16) float g_xl[NN * HD];
__device__ __align__(16) float g_xr[NN * HD];
__device__ int   g_deg[NN];
__device__ int   g_rowptr[NN + 1];
__device__ int   g_cursor[NN];
__device__ int   g_csrc[EDG];
__device__ int   g_bsum[64];
__device__ int   g_boff[64];
__device__ float g_pool[NG * DIM];
__device__ float g_cnt[NG];
// W hi/lo bf16 images: [L][n=512][k=64], n over [Wl | Wr] columns
__device__ __align__(16) __nv_bfloat16 g_bhi[NL * 512 * 64];
__device__ __align__(16) __nv_bfloat16 g_blo[NL * 512 * 64];

// ---------------- atom encoder ----------------------------------------------
__global__ void k_encoder(const int* __restrict__ feat, const float* __restrict__ emb) {
    int t = blockIdx.x * blockDim.x + threadIdx.x;
    if (t >= NN * DIM) return;
    int n = t >> 6, d = t & 63;
    const int offs[9] = {0, 119, 124, 136, 148, 158, 164, 170, 172};
    float s = 0.f;
#pragma unroll
    for (int j = 0; j < 9; j++) {
        int idx = feat[n * 9 + j] + offs[j];
        s += emb[idx * DIM + d];
    }
    g_x[t] = s;
}

// ---------------- CSR build --------------------------------------------------
__global__ void k_zerodeg() {
    int t = blockIdx.x * blockDim.x + threadIdx.x;
    if (t < NN) g_deg[t] = 0;
}
__global__ void k_hist(const int* __restrict__ dst) {
    int e = blockIdx.x * blockDim.x + threadIdx.x;
    if (e < EDG) atomicAdd(&g_deg[dst[e]], 1);
}
__global__ __launch_bounds__(SCAN_B) void k_scanA() {
    __shared__ int sh[SCAN_B];
    int b = blockIdx.x, t = threadIdx.x;
    int i = b * SCAN_B + t;
    int v = (i < NN) ? g_deg[i] : 0;
    sh[t] = v;
    __syncthreads();
    for (int o = 1; o < SCAN_B; o <<= 1) {
        int u = (t >= o) ? sh[t - o] : 0;
        __syncthreads();
        sh[t] += u;
        __syncthreads();
    }
    if (i < NN) g_rowptr[i] = sh[t] - v;
    if (t == SCAN_B - 1) g_bsum[b] = sh[t];
}
__global__ void k_scanB() {
    __shared__ int sh[64];
    int t = threadIdx.x;
    int v = (t < NSB) ? g_bsum[t] : 0;
    sh[t] = v;
    __syncthreads();
    for (int o = 1; o < 64; o <<= 1) {
        int u = (t >= o) ? sh[t - o] : 0;
        __syncthreads();
        sh[t] += u;
        __syncthreads();
    }
    g_boff[t] = sh[t] - v;
    if (t == NSB - 1) g_rowptr[NN] = sh[t];
}
__global__ void k_scanC() {
    int i = blockIdx.x * blockDim.x + threadIdx.x;
    if (i < NN) {
        int r = g_rowptr[i] + g_boff[i / SCAN_B];
        g_rowptr[i] = r;
        g_cursor[i] = r;
    }
}
__global__ void k_scatter(const int* __restrict__ src, const int* __restrict__ dst) {
    int e = blockIdx.x * blockDim.x + threadIdx.x;
    if (e < EDG) {
        int d = dst[e];
        int pos = atomicAdd(&g_cursor[d], 1);
        g_csrc[pos] = src[e];
    }
}

// ---------------- W -> bf16 hi/lo images [n][k] -------------------------------
__global__ void k_wprep(const float* __restrict__ Wl, const float* __restrict__ Wr) {
    int t = blockIdx.x * blockDim.x + threadIdx.x;   // NL*512*32 k-pairs
    if (t >= NL * 512 * 32) return;
    int kp = t & 31;
    int n = (t >> 5) & 511;
    int l = t >> 14;
    int k0 = kp * 2;
    const float* W = (n < 256) ? Wl : Wr;
    int nn = n & 255;
    float w0 = W[(l * 64 + k0) * 256 + nn];
    float w1 = W[(l * 64 + k0 + 1) * 256 + nn];
    __nv_bfloat16 h0 = __float2bfloat16(w0), h1 = __float2bfloat16(w1);
    __nv_bfloat16 l0 = __float2bfloat16(w0 - __bfloat162float(h0));
    __nv_bfloat16 l1 = __float2bfloat16(w1 - __bfloat162float(h1));
    __nv_bfloat162 hp; hp.x = h0; hp.y = h1;
    __nv_bfloat162 lp; lp.x = l0; lp.y = l1;
    size_t off = (size_t)l * 32768 + n * 64 + k0;
    *(__nv_bfloat162*)(g_bhi + off) = hp;
    *(__nv_bfloat162*)(g_blo + off) = lp;
}

// ---------------- HMMA GEMM: [xl|xr] = x @ [Wl|Wr] + bias ---------------------
// CTA: 64 rows, loops over 8 column-chunks of 64. Static smem 36,864B (<48KB).
// 4 warps (2m x 2n), warp tile 32x32. bf16 hi/lo split, fp32 accumulate.
// NOTE: weight images are indexed from DEVICE code via layer index (host code
// must never form g_bhi+offset — host shadow symbol, ATS makes it read zeros).
#define ASTR 72

__device__ __forceinline__ void mma16816(float c[4], u32 a0, u32 a1, u32 a2, u32 a3,
                                         u32 b0, u32 b1) {
    asm volatile("mma.sync.aligned.m16n8k16.row.col.f32.bf16.bf16.f32 "
                 "{%0,%1,%2,%3}, {%4,%5,%6,%7}, {%8,%9}, {%0,%1,%2,%3};"
                 : "+f"(c[0]), "+f"(c[1]), "+f"(c[2]), "+f"(c[3])
                 : "r"(a0), "r"(a1), "r"(a2), "r"(a3), "r"(b0), "r"(b1));
}

__global__ __launch_bounds__(128) void k_gemm_mma(int layer,
                                                  const float* __restrict__ bl,
                                                  const float* __restrict__ br) {
    __shared__ __nv_bfloat16 sAhi[64 * ASTR];
    __shared__ __nv_bfloat16 sAlo[64 * ASTR];
    __shared__ __nv_bfloat16 sBhi[64 * ASTR];
    __shared__ __nv_bfloat16 sBlo[64 * ASTR];

    const __nv_bfloat16* Bhi = g_bhi + (size_t)layer * 32768;
    const __nv_bfloat16* Blo = g_blo + (size_t)layer * 32768;

    int tid = threadIdx.x;
    int bm = blockIdx.x * 64;

    // A: 64x64 fp32 -> bf16 hi/lo (once per CTA)
    for (int i = tid; i < 64 * 32; i += 128) {
        int m = i >> 5, kp = i & 31;
        int row = bm + m;
        float2 v = make_float2(0.f, 0.f);
        if (row < NN) v = *(const float2*)(g_x + (size_t)row * DIM + kp * 2);
        __nv_bfloat16 h0 = __float2bfloat16(v.x), h1 = __float2bfloat16(v.y);
        __nv_bfloat16 l0 = __float2bfloat16(v.x - __bfloat162float(h0));
        __nv_bfloat16 l1 = __float2bfloat16(v.y - __bfloat162float(h1));
        __nv_bfloat162 hp; hp.x = h0; hp.y = h1;
        __nv_bfloat162 lp; lp.x = l0; lp.y = l1;
        *(__nv_bfloat162*)&sAhi[m * ASTR + kp * 2] = hp;
        *(__nv_bfloat162*)&sAlo[m * ASTR + kp * 2] = lp;
    }

    int wid = tid >> 5, lane = tid & 31;
    int wm = wid >> 1, wn = wid & 1;     // 2x2 warps, warp tile 32x32
    int gq = lane >> 2, tq = lane & 3;

    for (int nc = 0; nc < 8; nc++) {
        int bc = nc * 64;
        __syncthreads();   // iter0: publish A; later: protect B reuse
        // B chunk: 64 cols x 64 k, hi/lo
        for (int i = tid; i < 64 * 32; i += 128) {
            int n = i >> 5, kp = i & 31;
            size_t go = (size_t)(bc + n) * 64 + kp * 2;
            *(u32*)&sBhi[n * ASTR + kp * 2] = *(const u32*)(Bhi + go);
            *(u32*)&sBlo[n * ASTR + kp * 2] = *(const u32*)(Blo + go);
        }
        __syncthreads();

        float C[2][4][4];
#pragma unroll
        for (int i = 0; i < 2; i++)
#pragma unroll
            for (int j = 0; j < 4; j++)
#pragma unroll
                for (int q = 0; q < 4; q++) C[i][j][q] = 0.f;

#pragma unroll
        for (int pass = 0; pass < 3; pass++) {
            const __nv_bfloat16* A = (pass == 2) ? sAlo : sAhi;
            const __nv_bfloat16* B = (pass == 1) ? sBlo : sBhi;
#pragma unroll
            for (int kk = 0; kk < 4; kk++) {
                int k0 = kk * 16 + tq * 2;
                u32 a[2][4];
#pragma unroll
                for (int i = 0; i < 2; i++) {
                    int r = wm * 32 + i * 16 + gq;
                    a[i][0] = *(const u32*)&A[r * ASTR + k0];
                    a[i][1] = *(const u32*)&A[(r + 8) * ASTR + k0];
                    a[i][2] = *(const u32*)&A[r * ASTR + k0 + 8];
                    a[i][3] = *(const u32*)&A[(r + 8) * ASTR + k0 + 8];
                }
                u32 b[4][2];
#pragma unroll
                for (int j = 0; j < 4; j++) {
                    int c = wn * 32 + j * 8 + gq;
                    b[j][0] = *(const u32*)&B[c * ASTR + k0];
                    b[j][1] = *(const u32*)&B[c * ASTR + k0 + 8];
                }
#pragma unroll
                for (int i = 0; i < 2; i++)
#pragma unroll
                    for (int j = 0; j < 4; j++)
                        mma16816(C[i][j], a[i][0], a[i][1], a[i][2], a[i][3], b[j][0], b[j][1]);
            }
        }

        // epilogue: bias + store this 64-col chunk
#pragma unroll
        for (int j = 0; j < 4; j++) {
            int col = bc + wn * 32 + j * 8 + tq * 2;   // 0..511
            float* base; const float* bias;
            if (col < 256) { base = g_xl; bias = bl; }
            else           { base = g_xr; bias = br; col -= 256; }
            float b0 = bias[col], b1 = bias[col + 1];
#pragma unroll
            for (int i = 0; i < 2; i++) {
                int r0 = bm + wm * 32 + i * 16 + gq;
                if (r0 < NN)
                    *(float2*)(base + (size_t)r0 * HD + col) = make_float2(C[i][j][0] + b0, C[i][j][1] + b1);
                int r1 = r0 + 8;
                if (r1 < NN)
                    *(float2*)(base + (size_t)r1 * HD + col) = make_float2(C[i][j][2] + b0, C[i][j][3] + b1);
            }
        }
    }
}

// ---------------- fused attention --------------------------------------------
__device__ __forceinline__ float lrelu(float v) { return v > 0.f ? v : 0.2f * v; }

__device__ __forceinline__ float edge_score(float4 ta, float4 tb,
                                            float4 xra, float4 xrb,
                                            float4 ata, float4 atb) {
    float p = lrelu(ta.x + xra.x) * ata.x + lrelu(ta.y + xra.y) * ata.y
            + lrelu(ta.z + xra.z) * ata.z + lrelu(ta.w + xra.w) * ata.w
            + lrelu(tb.x + xrb.x) * atb.x + lrelu(tb.y + xrb.y) * atb.y
            + lrelu(tb.z + xrb.z) * atb.z + lrelu(tb.w + xrb.w) * atb.w;
    p += __shfl_xor_sync(0xffffffffu, p, 1);
    p += __shfl_xor_sync(0xffffffffu, p, 2);
    p += __shfl_xor_sync(0xffffffffu, p, 4);
    return p;
}

__global__ __launch_bounds__(256) void k_attn(const float* __restrict__ att,
                                              const float* __restrict__ gb, int dogelu) {
    int w = (blockIdx.x * blockDim.x + threadIdx.x) >> 5;
    int lane = threadIdx.x & 31;
    if (w >= NN) return;

    const float4* xr4 = (const float4*)(g_xr + (size_t)w * HD);
    float4 xra = xr4[2 * lane], xrb = xr4[2 * lane + 1];
    const float4* at4 = (const float4*)att;
    float4 ata = at4[2 * lane], atb = at4[2 * lane + 1];

    const float4* xs4 = (const float4*)(g_xl + (size_t)w * HD);
    float4 sa = xs4[2 * lane], sb = xs4[2 * lane + 1];

    int beg = g_rowptr[w], end = g_rowptr[w + 1];
    int j = beg;
    bool have = (j < end);
    float4 na, nb;
    if (have) {
        int s = g_csrc[j];
        const float4* p = (const float4*)(g_xl + (size_t)s * HD);
        na = p[2 * lane]; nb = p[2 * lane + 1];
    }

    float denom;
    float acc[8];
    {
        float e = edge_score(sa, sb, xra, xrb, ata, atb);
        float ea = __expf(e);
        denom = ea;
        acc[0] = ea * sa.x; acc[1] = ea * sa.y; acc[2] = ea * sa.z; acc[3] = ea * sa.w;
        acc[4] = ea * sb.x; acc[5] = ea * sb.y; acc[6] = ea * sb.z; acc[7] = ea * sb.w;
    }
    while (have) {
        float4 ta = na, tb = nb;
        j++;
        have = (j < end);
        if (have) {
            int s = g_csrc[j];
            const float4* p = (const float4*)(g_xl + (size_t)s * HD);
            na = p[2 * lane]; nb = p[2 * lane + 1];
        }
        float e = edge_score(ta, tb, xra, xrb, ata, atb);
        float ea = __expf(e);
        denom += ea;
        acc[0] += ea * ta.x; acc[1] += ea * ta.y; acc[2] += ea * ta.z; acc[3] += ea * ta.w;
        acc[4] += ea * tb.x; acc[5] += ea * tb.y; acc[6] += ea * tb.z; acc[7] += ea * tb.w;
    }

    float inv = 1.f / denom;
    float r[8];
#pragma unroll
    for (int c = 0; c < 8; c++) {
        float v = acc[c] * inv;
        v += __shfl_xor_sync(0xffffffffu, v, 8);
        v += __shfl_xor_sync(0xffffffffu, v, 16);
        v *= 0.25f;
        r[c] = v;
    }
    int d0 = 8 * (lane & 7);
#pragma unroll
    for (int c = 0; c < 8; c++) {
        float s = r[c] + gb[d0 + c];
        if (dogelu) s = 0.5f * s * (1.f + erff(s * 0.70710678118654752f));
        r[c] = s;
    }
    if (lane < 8) {
        *(float4*)(g_x + (size_t)w * DIM + d0)     = make_float4(r[0], r[1], r[2], r[3]);
        *(float4*)(g_x + (size_t)w * DIM + d0 + 4) = make_float4(r[4], r[5], r[6], r[7]);
    }
}

// ---------------- pool + head ------------------------------------------------
__global__ void k_poolzero() {
    int t = blockIdx.x * blockDim.x + threadIdx.x;
    if (t < NG * DIM) g_pool[t] = 0.f;
    if (t < NG) g_cnt[t] = 0.f;
}
__global__ void k_pool(const int* __restrict__ batch) {
    int t = blockIdx.x * blockDim.x + threadIdx.x;
    if (t >= NN * DIM) return;
    int n = t >> 6, d = t & 63;
    int gidx = batch[n];
    atomicAdd(&g_pool[gidx * DIM + d], g_x[t]);
    if (d == 0) atomicAdd(&g_cnt[gidx], 1.f);
}
__global__ void k_final(const float* __restrict__ Wc, const float* __restrict__ bc,
                        float* __restrict__ out) {
    int g = blockIdx.x;
    int lane = threadIdx.x;
    float inv = 1.f / fmaxf(g_cnt[g], 1.f);
    float p0 = g_pool[g * DIM + lane] * inv;
    float p1 = g_pool[g * DIM + 32 + lane] * inv;
#pragma unroll
    for (int c = 0; c < NC; c++) {
        float s = p0 * Wc[lane * NC + c] + p1 * Wc[(lane + 32) * NC + c];
#pragma unroll
        for (int o = 16; o; o >>= 1) s += __shfl_xor_sync(0xffffffffu, s, o);
        if (lane == 0) out[g * NC + c] = s + bc[c];
    }
}

// ---------------- launch ------------------------------------------------------
extern "C" void kernel_launch(void* const* d_in, const int* in_sizes, int n_in,
                              void* d_out, int out_size) {
    (void)in_sizes; (void)n_in; (void)out_size;
    const int*   feat  = (const int*)  d_in[0];
    const int*   econ  = (const int*)  d_in[1];
    const int*   batch = (const int*)  d_in[2];
    const float* emb   = (const float*)d_in[3];
    const float* Wl    = (const float*)d_in[4];
    const float* bl    = (const float*)d_in[5];
    const float* Wr    = (const float*)d_in[6];
    const float* br    = (const float*)d_in[7];
    const float* att   = (const float*)d_in[8];
    const float* gbias = (const float*)d_in[9];
    const float* Wc    = (const float*)d_in[10];
    const float* bcv   = (const float*)d_in[11];
    float* out = (float*)d_out;

    const int* src = econ;
    const int* dst = econ + EDG;

    k_encoder<<<(NN * DIM + 255) / 256, 256>>>(feat, emb);

    k_zerodeg<<<(NN + 255) / 256, 256>>>();
    k_hist<<<(EDG + 255) / 256, 256>>>(dst);
    k_scanA<<<NSB, SCAN_B>>>();
    k_scanB<<<1, 64>>>();
    k_scanC<<<(NN + 255) / 256, 256>>>();
    k_scatter<<<(EDG + 255) / 256, 256>>>(src, dst);

    k_wprep<<<(NL * 512 * 32 + 255) / 256, 256>>>(Wl, Wr);

    for (int l = 0; l < NL; l++) {
        k_gemm_mma<<<(NN + 63) / 64, 128>>>(l, bl + l * HD, br + l * HD);
        k_attn<<<(NN * 32 + 255) / 256, 256>>>(att + l * NH * DIM, gbias + l * DIM,
                                               (l < NL - 1) ? 1 : 0);
    }

    k_poolzero<<<(NG * DIM + 255) / 256, 256>>>();
    k_pool<<<(NN * DIM + 255) / 256, 256>>>(batch);
    k_final<<<NG, 32>>>(Wc, bcv, out);
}

// round 9
// speedup vs baseline: 3.6993x; 1.0454x over previous
#include <cuda_runtime.h>
#include <cuda_bf16.h>
#include <math.h>
#include <cstdint>

#define NN 50000
#define EDG 400000
#define DIM 64
#define NH 4
#define HD 256
#define NL 3
#define NC 10
#define NG 512
#define SCAN_B 1024
#define NSB ((NN + SCAN_B - 1) / SCAN_B)

typedef unsigned long long u64;
typedef unsigned int u32;

// ---------------- scratch ----------------------------------------------------
__device__ __align__(16) float g_x[NN * DIM];
__device__ __align__(16) float g_xl[NN * HD];
__device__ __align__(16) float g_xr[NN * HD];
__device__ int   g_deg[NN];
__device__ int   g_rowptr[NN + 1];
__device__ int   g_cursor[NN];
__device__ int   g_csrc[EDG];
__device__ int   g_bsum[64];
__device__ int   g_boff[64];
__device__ float g_pool[NG * DIM];
__device__ float g_cnt[NG];
// W hi/lo bf16 images: [L][n=512][k=64], n over [Wl | Wr] columns
__device__ __align__(16) __nv_bfloat16 g_bhi[NL * 512 * 64];
__device__ __align__(16) __nv_bfloat16 g_blo[NL * 512 * 64];

// ---------------- atom encoder (+ scratch zeroing) ---------------------------
__global__ void k_encoder(const int* __restrict__ feat, const float* __restrict__ emb) {
    int t = blockIdx.x * blockDim.x + threadIdx.x;
    if (t < NN) g_deg[t] = 0;
    if (t < NG * DIM) g_pool[t] = 0.f;
    if (t < NG) g_cnt[t] = 0.f;
    if (t >= NN * DIM) return;
    int n = t >> 6, d = t & 63;
    const int offs[9] = {0, 119, 124, 136, 148, 158, 164, 170, 172};
    float s = 0.f;
#pragma unroll
    for (int j = 0; j < 9; j++) {
        int idx = feat[n * 9 + j] + offs[j];
        s += emb[idx * DIM + d];
    }
    g_x[t] = s;
}

// ---------------- CSR build --------------------------------------------------
__global__ void k_hist(const int* __restrict__ dst) {
    int e = blockIdx.x * blockDim.x + threadIdx.x;
    if (e < EDG) atomicAdd(&g_deg[dst[e]], 1);
}
__global__ __launch_bounds__(SCAN_B) void k_scanA() {
    __shared__ int sh[SCAN_B];
    int b = blockIdx.x, t = threadIdx.x;
    int i = b * SCAN_B + t;
    int v = (i < NN) ? g_deg[i] : 0;
    sh[t] = v;
    __syncthreads();
    for (int o = 1; o < SCAN_B; o <<= 1) {
        int u = (t >= o) ? sh[t - o] : 0;
        __syncthreads();
        sh[t] += u;
        __syncthreads();
    }
    if (i < NN) g_rowptr[i] = sh[t] - v;
    if (t == SCAN_B - 1) g_bsum[b] = sh[t];
}
__global__ void k_scanB() {
    __shared__ int sh[64];
    int t = threadIdx.x;
    int v = (t < NSB) ? g_bsum[t] : 0;
    sh[t] = v;
    __syncthreads();
    for (int o = 1; o < 64; o <<= 1) {
        int u = (t >= o) ? sh[t - o] : 0;
        __syncthreads();
        sh[t] += u;
        __syncthreads();
    }
    g_boff[t] = sh[t] - v;
    if (t == NSB - 1) g_rowptr[NN] = sh[t];
}
__global__ void k_scanC() {
    int i = blockIdx.x * blockDim.x + threadIdx.x;
    if (i < NN) {
        int r = g_rowptr[i] + g_boff[i / SCAN_B];
        g_rowptr[i] = r;
        g_cursor[i] = r;
    }
}
__global__ void k_scatter(const int* __restrict__ src, const int* __restrict__ dst) {
    int e = blockIdx.x * blockDim.x + threadIdx.x;
    if (e < EDG) {
        int d = dst[e];
        int pos = atomicAdd(&g_cursor[d], 1);
        g_csrc[pos] = src[e];
    }
}

// ---------------- W -> bf16 hi/lo images [n][k] -------------------------------
__global__ void k_wprep(const float* __restrict__ Wl, const float* __restrict__ Wr) {
    int t = blockIdx.x * blockDim.x + threadIdx.x;   // NL*512*32 k-pairs
    if (t >= NL * 512 * 32) return;
    int kp = t & 31;
    int n = (t >> 5) & 511;
    int l = t >> 14;
    int k0 = kp * 2;
    const float* W = (n < 256) ? Wl : Wr;
    int nn = n & 255;
    float w0 = W[(l * 64 + k0) * 256 + nn];
    float w1 = W[(l * 64 + k0 + 1) * 256 + nn];
    __nv_bfloat16 h0 = __float2bfloat16(w0), h1 = __float2bfloat16(w1);
    __nv_bfloat16 l0 = __float2bfloat16(w0 - __bfloat162float(h0));
    __nv_bfloat16 l1 = __float2bfloat16(w1 - __bfloat162float(h1));
    __nv_bfloat162 hp; hp.x = h0; hp.y = h1;
    __nv_bfloat162 lp; lp.x = l0; lp.y = l1;
    size_t off = (size_t)l * 32768 + n * 64 + k0;
    *(__nv_bfloat162*)(g_bhi + off) = hp;
    *(__nv_bfloat162*)(g_blo + off) = lp;
}

// ---------------- HMMA GEMM: [xl|xr] = x @ [Wl|Wr] + bias ---------------------
// CTA: 128 rows, loops over 8 column-chunks of 64. Dynamic smem 55,296B.
// 8 warps (4m x 2n), warp tile 32x32. bf16 hi/lo split, fp32 accumulate.
// Weight images indexed from DEVICE code via layer index (host shadow-symbol trap).
#define ASTR 72
#define GSMEM ((128 * ASTR * 2 + 64 * ASTR * 2) * 2)   // 55296 bytes

__device__ __forceinline__ void mma16816(float c[4], u32 a0, u32 a1, u32 a2, u32 a3,
                                         u32 b0, u32 b1) {
    asm volatile("mma.sync.aligned.m16n8k16.row.col.f32.bf16.bf16.f32 "
                 "{%0,%1,%2,%3}, {%4,%5,%6,%7}, {%8,%9}, {%0,%1,%2,%3};"
                 : "+f"(c[0]), "+f"(c[1]), "+f"(c[2]), "+f"(c[3])
                 : "r"(a0), "r"(a1), "r"(a2), "r"(a3), "r"(b0), "r"(b1));
}

__global__ __launch_bounds__(256) void k_gemm_mma(int layer,
                                                  const float* __restrict__ bl,
                                                  const float* __restrict__ br) {
    extern __shared__ __nv_bfloat16 smem[];
    __nv_bfloat16* sAhi = smem;                    // 128*ASTR
    __nv_bfloat16* sAlo = sAhi + 128 * ASTR;
    __nv_bfloat16* sBhi = sAlo + 128 * ASTR;       // 64*ASTR
    __nv_bfloat16* sBlo = sBhi + 64 * ASTR;

    const __nv_bfloat16* Bhi = g_bhi + (size_t)layer * 32768;
    const __nv_bfloat16* Blo = g_blo + (size_t)layer * 32768;

    int tid = threadIdx.x;
    int bm = blockIdx.x * 128;

    // A: 128x64 fp32 -> bf16 hi/lo (once per CTA)
    for (int i = tid; i < 128 * 32; i += 256) {
        int m = i >> 5, kp = i & 31;
        int row = bm + m;
        float2 v = make_float2(0.f, 0.f);
        if (row < NN) v = *(const float2*)(g_x + (size_t)row * DIM + kp * 2);
        __nv_bfloat16 h0 = __float2bfloat16(v.x), h1 = __float2bfloat16(v.y);
        __nv_bfloat16 l0 = __float2bfloat16(v.x - __bfloat162float(h0));
        __nv_bfloat16 l1 = __float2bfloat16(v.y - __bfloat162float(h1));
        __nv_bfloat162 hp; hp.x = h0; hp.y = h1;
        __nv_bfloat162 lp; lp.x = l0; lp.y = l1;
        *(__nv_bfloat162*)&sAhi[m * ASTR + kp * 2] = hp;
        *(__nv_bfloat162*)&sAlo[m * ASTR + kp * 2] = lp;
    }

    int wid = tid >> 5, lane = tid & 31;
    int wm = wid >> 1, wn = wid & 1;     // 4x2 warps, warp tile 32x32
    int gq = lane >> 2, tq = lane & 3;

    for (int nc = 0; nc < 8; nc++) {
        int bc = nc * 64;
        __syncthreads();   // iter0: publish A; later: protect B reuse
        // B chunk: 64 cols x 64 k, hi/lo
        for (int i = tid; i < 64 * 32; i += 256) {
            int n = i >> 5, kp = i & 31;
            size_t go = (size_t)(bc + n) * 64 + kp * 2;
            *(u32*)&sBhi[n * ASTR + kp * 2] = *(const u32*)(Bhi + go);
            *(u32*)&sBlo[n * ASTR + kp * 2] = *(const u32*)(Blo + go);
        }
        __syncthreads();

        float C[2][4][4];
#pragma unroll
        for (int i = 0; i < 2; i++)
#pragma unroll
            for (int j = 0; j < 4; j++)
#pragma unroll
                for (int q = 0; q < 4; q++) C[i][j][q] = 0.f;

#pragma unroll
        for (int pass = 0; pass < 3; pass++) {
            const __nv_bfloat16* A = (pass == 2) ? sAlo : sAhi;
            const __nv_bfloat16* B = (pass == 1) ? sBlo : sBhi;
#pragma unroll
            for (int kk = 0; kk < 4; kk++) {
                int k0 = kk * 16 + tq * 2;
                u32 a[2][4];
#pragma unroll
                for (int i = 0; i < 2; i++) {
                    int r = wm * 32 + i * 16 + gq;
                    a[i][0] = *(const u32*)&A[r * ASTR + k0];
                    a[i][1] = *(const u32*)&A[(r + 8) * ASTR + k0];
                    a[i][2] = *(const u32*)&A[r * ASTR + k0 + 8];
                    a[i][3] = *(const u32*)&A[(r + 8) * ASTR + k0 + 8];
                }
                u32 b[4][2];
#pragma unroll
                for (int j = 0; j < 4; j++) {
                    int c = wn * 32 + j * 8 + gq;
                    b[j][0] = *(const u32*)&B[c * ASTR + k0];
                    b[j][1] = *(const u32*)&B[c * ASTR + k0 + 8];
                }
#pragma unroll
                for (int i = 0; i < 2; i++)
#pragma unroll
                    for (int j = 0; j < 4; j++)
                        mma16816(C[i][j], a[i][0], a[i][1], a[i][2], a[i][3], b[j][0], b[j][1]);
            }
        }

        // epilogue: bias + store this 64-col chunk
#pragma unroll
        for (int j = 0; j < 4; j++) {
            int col = bc + wn * 32 + j * 8 + tq * 2;   // 0..511
            float* base; const float* bias;
            if (col < 256) { base = g_xl; bias = bl; }
            else           { base = g_xr; bias = br; col -= 256; }
            float b0 = bias[col], b1 = bias[col + 1];
#pragma unroll
            for (int i = 0; i < 2; i++) {
                int r0 = bm + wm * 32 + i * 16 + gq;
                if (r0 < NN)
                    *(float2*)(base + (size_t)r0 * HD + col) = make_float2(C[i][j][0] + b0, C[i][j][1] + b1);
                int r1 = r0 + 8;
                if (r1 < NN)
                    *(float2*)(base + (size_t)r1 * HD + col) = make_float2(C[i][j][2] + b0, C[i][j][3] + b1);
            }
        }
    }
}

// ---------------- fused attention --------------------------------------------
__device__ __forceinline__ float lrelu(float v) { return v > 0.f ? v : 0.2f * v; }

__device__ __forceinline__ float edge_score(float4 ta, float4 tb,
                                            float4 xra, float4 xrb,
                                            float4 ata, float4 atb) {
    float p = lrelu(ta.x + xra.x) * ata.x + lrelu(ta.y + xra.y) * ata.y
            + lrelu(ta.z + xra.z) * ata.z + lrelu(ta.w + xra.w) * ata.w
            + lrelu(tb.x + xrb.x) * atb.x + lrelu(tb.y + xrb.y) * atb.y
            + lrelu(tb.z + xrb.z) * atb.z + lrelu(tb.w + xrb.w) * atb.w;
    p += __shfl_xor_sync(0xffffffffu, p, 1);
    p += __shfl_xor_sync(0xffffffffu, p, 2);
    p += __shfl_xor_sync(0xffffffffu, p, 4);
    return p;
}

__global__ __launch_bounds__(256) void k_attn(const float* __restrict__ att,
                                              const float* __restrict__ gb, int dogelu) {
    int w = (blockIdx.x * blockDim.x + threadIdx.x) >> 5;
    int lane = threadIdx.x & 31;
    if (w >= NN) return;

    const float4* xr4 = (const float4*)(g_xr + (size_t)w * HD);
    float4 xra = xr4[2 * lane], xrb = xr4[2 * lane + 1];
    const float4* at4 = (const float4*)att;
    float4 ata = at4[2 * lane], atb = at4[2 * lane + 1];

    const float4* xs4 = (const float4*)(g_xl + (size_t)w * HD);
    float4 sa = xs4[2 * lane], sb = xs4[2 * lane + 1];

    int beg = g_rowptr[w], end = g_rowptr[w + 1];
    int j = beg;
    bool have = (j < end);
    // pipeline: index fetched one step ahead of data
    int snext = (j + 1 < end) ? g_csrc[j + 1] : 0;
    float4 na, nb;
    if (have) {
        int s = g_csrc[j];
        const float4* p = (const float4*)(g_xl + (size_t)s * HD);
        na = p[2 * lane]; nb = p[2 * lane + 1];
    }

    float denom;
    float acc[8];
    {
        float e = edge_score(sa, sb, xra, xrb, ata, atb);
        float ea = __expf(e);
        denom = ea;
        acc[0] = ea * sa.x; acc[1] = ea * sa.y; acc[2] = ea * sa.z; acc[3] = ea * sa.w;
        acc[4] = ea * sb.x; acc[5] = ea * sb.y; acc[6] = ea * sb.z; acc[7] = ea * sb.w;
    }
    while (have) {
        float4 ta = na, tb = nb;
        j++;
        have = (j < end);
        int s = snext;
        snext = (j + 1 < end) ? g_csrc[j + 1] : 0;
        if (have) {
            const float4* p = (const float4*)(g_xl + (size_t)s * HD);
            na = p[2 * lane]; nb = p[2 * lane + 1];
        }
        float e = edge_score(ta, tb, xra, xrb, ata, atb);
        float ea = __expf(e);
        denom += ea;
        acc[0] += ea * ta.x; acc[1] += ea * ta.y; acc[2] += ea * ta.z; acc[3] += ea * ta.w;
        acc[4] += ea * tb.x; acc[5] += ea * tb.y; acc[6] += ea * tb.z; acc[7] += ea * tb.w;
    }

    float inv = 1.f / denom;
    float r[8];
#pragma unroll
    for (int c = 0; c < 8; c++) {
        float v = acc[c] * inv;
        v += __shfl_xor_sync(0xffffffffu, v, 8);
        v += __shfl_xor_sync(0xffffffffu, v, 16);
        v *= 0.25f;
        r[c] = v;
    }
    int d0 = 8 * (lane & 7);
#pragma unroll
    for (int c = 0; c < 8; c++) {
        float s = r[c] + gb[d0 + c];
        if (dogelu) s = 0.5f * s * (1.f + erff(s * 0.70710678118654752f));
        r[c] = s;
    }
    if (lane < 8) {
        *(float4*)(g_x + (size_t)w * DIM + d0)     = make_float4(r[0], r[1], r[2], r[3]);
        *(float4*)(g_x + (size_t)w * DIM + d0 + 4) = make_float4(r[4], r[5], r[6], r[7]);
    }
}

// ---------------- pool + head ------------------------------------------------
__global__ void k_pool(const int* __restrict__ batch) {
    int t = blockIdx.x * blockDim.x + threadIdx.x;
    if (t >= NN * DIM) return;
    int n = t >> 6, d = t & 63;
    int gidx = batch[n];
    atomicAdd(&g_pool[gidx * DIM + d], g_x[t]);
    if (d == 0) atomicAdd(&g_cnt[gidx], 1.f);
}
__global__ void k_final(const float* __restrict__ Wc, const float* __restrict__ bc,
                        float* __restrict__ out) {
    int g = blockIdx.x;
    int lane = threadIdx.x;
    float inv = 1.f / fmaxf(g_cnt[g], 1.f);
    float p0 = g_pool[g * DIM + lane] * inv;
    float p1 = g_pool[g * DIM + 32 + lane] * inv;
#pragma unroll
    for (int c = 0; c < NC; c++) {
        float s = p0 * Wc[lane * NC + c] + p1 * Wc[(lane + 32) * NC + c];
#pragma unroll
        for (int o = 16; o; o >>= 1) s += __shfl_xor_sync(0xffffffffu, s, o);
        if (lane == 0) out[g * NC + c] = s + bc[c];
    }
}

// ---------------- launch ------------------------------------------------------
extern "C" void kernel_launch(void* const* d_in, const int* in_sizes, int n_in,
                              void* d_out, int out_size) {
    (void)in_sizes; (void)n_in; (void)out_size;
    const int*   feat  = (const int*)  d_in[0];
    const int*   econ  = (const int*)  d_in[1];
    const int*   batch = (const int*)  d_in[2];
    const float* emb   = (const float*)d_in[3];
    const float* Wl    = (const float*)d_in[4];
    const float* bl    = (const float*)d_in[5];
    const float* Wr    = (const float*)d_in[6];
    const float* br    = (const float*)d_in[7];
    const float* att   = (const float*)d_in[8];
    const float* gbias = (const float*)d_in[9];
    const float* Wc    = (const float*)d_in[10];
    const float* bcv   = (const float*)d_in[11];
    float* out = (float*)d_out;

    const int* src = econ;
    const int* dst = econ + EDG;

    cudaFuncSetAttribute(k_gemm_mma, cudaFuncAttributeMaxDynamicSharedMemorySize, GSMEM);

    k_encoder<<<(NN * DIM + 255) / 256, 256>>>(feat, emb);

    k_hist<<<(EDG + 255) / 256, 256>>>(dst);
    k_scanA<<<NSB, SCAN_B>>>();
    k_scanB<<<1, 64>>>();
    k_scanC<<<(NN + 255) / 256, 256>>>();
    k_scatter<<<(EDG + 255) / 256, 256>>>(src, dst);

    k_wprep<<<(NL * 512 * 32 + 255) / 256, 256>>>(Wl, Wr);

    for (int l = 0; l < NL; l++) {
        k_gemm_mma<<<(NN + 127) / 128, 256, GSMEM>>>(l, bl + l * HD, br + l * HD);
        k_attn<<<(NN * 32 + 255) / 256, 256>>>(att + l * NH * DIM, gbias + l * DIM,
                                               (l < NL - 1) ? 1 : 0);
    }

    k_pool<<<(NN * DIM + 255) / 256, 256>>>(batch);
    k_final<<<NG, 32>>>(Wc, bcv, out);
}